// round 1
// baseline (speedup 1.0000x reference)
#include <cuda_runtime.h>
#include <cstddef>

// Problem dims (fixed by the problem)
#define T_STEPS 128
#define BATCH   2048
#define IN0     18
#define H       256
#define G3      768   // 3*H
#define NB      16    // batch rows per block
#define NBLK    (BATCH / NB)   // 128 blocks
#define NTHR    256   // one thread per hidden unit j

typedef unsigned long long u64;

// ---------------- scratch (static __device__, no allocations) ----------------
__device__ float g_Wt_hh0[H * G3];   // W_hh0 transposed to [k][g]
__device__ float g_Wt_hh1[H * G3];
__device__ float g_Wt_ih1[H * G3];
// layer-0 outputs, tiled layout: [t][blk][c][b]  (c = hidden channel, b = 0..15)
__device__ float g_h1[(size_t)T_STEPS * NBLK * H * NB];
__device__ float g_h2[BATCH * H];    // layer-1 final hidden, [b][c]

// ---------------- packed fp32x2 helpers (Blackwell FFMA2) ----------------
__device__ __forceinline__ u64 pk2(float a, float b) {
    u64 r; asm("mov.b64 %0, {%1, %2};" : "=l"(r) : "f"(a), "f"(b)); return r;
}
__device__ __forceinline__ void fma2(u64& d, u64 a, u64 b) {
    asm("fma.rn.f32x2 %0, %1, %2, %0;" : "+l"(d) : "l"(a), "l"(b));
}
__device__ __forceinline__ float2 up2(u64 p) {
    float2 f; asm("mov.b64 {%0, %1}, %2;" : "=f"(f.x), "=f"(f.y) : "l"(p)); return f;
}

__device__ __forceinline__ float sigf(float x) {
    return __fdividef(1.f, 1.f + __expf(-x));
}
__device__ __forceinline__ float tanhf_fast(float x) {
    return 2.f * sigf(2.f * x) - 1.f;
}

// ---------------- transpose [768x256] -> [256x768] ----------------
__global__ void k_transpose(const float* __restrict__ src, int which) {
    float* dst = (which == 0) ? g_Wt_hh0 : (which == 1) ? g_Wt_hh1 : g_Wt_ih1;
    int idx = blockIdx.x * 256 + threadIdx.x;   // grid = 768 blocks, exact
    int k = idx / G3;
    int g = idx - k * G3;
    dst[idx] = src[g * H + k];
}

// Core hidden GEMM: acc[g][b] += sum_k sbuf[k][b] * Wt[k][g]  for g in {j, H+j, 2H+j}
__device__ __forceinline__ void gemm_k(const float* __restrict__ Wt,
                                       const float* sbuf,  // smem, [k][NB] layout
                                       u64* __restrict__ ar, u64* __restrict__ az,
                                       u64* __restrict__ an, int j) {
#pragma unroll 4
    for (int k = 0; k < H; k++) {
        const float* wp = Wt + k * G3 + j;
        float wr = wp[0], wz = wp[H], wn = wp[2 * H];
        u64 wr2 = pk2(wr, wr), wz2 = pk2(wz, wz), wn2 = pk2(wn, wn);
        const ulonglong2* hp = (const ulonglong2*)(sbuf + k * NB);
#pragma unroll
        for (int q = 0; q < 4; q++) {
            ulonglong2 hq = hp[q];
            fma2(ar[2 * q],     hq.x, wr2);
            fma2(ar[2 * q + 1], hq.y, wr2);
            fma2(az[2 * q],     hq.x, wz2);
            fma2(az[2 * q + 1], hq.y, wz2);
            fma2(an[2 * q],     hq.x, wn2);
            fma2(an[2 * q + 1], hq.y, wn2);
        }
    }
}

// ---------------- layer 0: fused input proj (K=18, smem weights) + recurrence ----------------
__global__ __launch_bounds__(NTHR, 1)
void k_gru0(const float* __restrict__ x, const float* __restrict__ Wih,
            const float* __restrict__ bih, const float* __restrict__ bhh) {
    extern __shared__ float smem[];
    float* sWih = smem;                    // [i][g], 18*768 = 13824 floats
    float* sh_h = smem + IN0 * G3;         // [c][b], 256*16  = 4096 floats
    float* sx   = sh_h + H * NB;           // [i][b], 18*16   = 288 floats

    const int j = threadIdx.x;
    const int bbase = blockIdx.x * NB;

    // stage W_ih0 transposed into smem
    for (int idx = j; idx < IN0 * G3; idx += NTHR) {
        int i = idx / G3, g = idx - i * G3;
        sWih[idx] = Wih[g * IN0 + i];
    }
    for (int idx = j; idx < H * NB; idx += NTHR) sh_h[idx] = 0.f;

    float hreg[NB];
#pragma unroll
    for (int b = 0; b < NB; b++) hreg[b] = 0.f;

    const float brz = bih[j] + bhh[j];
    const float bzz = bih[H + j] + bhh[H + j];
    const float bxn = bih[2 * H + j];
    const float bhn = bhh[2 * H + j];
    __syncthreads();

    for (int t = 0; t < T_STEPS; t++) {
        // stage x[t] tile, transposed to [i][b]
        for (int idx = j; idx < IN0 * NB; idx += NTHR) {
            int b = idx / IN0, i = idx - b * IN0;
            sx[i * NB + b] = x[((size_t)(t * BATCH) + bbase + b) * IN0 + i];
        }
        __syncthreads();

        u64 ar[8], az[8], axn[8], ahn[8];
#pragma unroll
        for (int p = 0; p < 8; p++) {
            ar[p] = pk2(brz, brz); az[p] = pk2(bzz, bzz);
            axn[p] = pk2(bxn, bxn); ahn[p] = pk2(bhn, bhn);
        }

        // input projection, K = 18 (smem weights)
#pragma unroll
        for (int i = 0; i < IN0; i++) {
            float wr = sWih[i * G3 + j];
            float wz = sWih[i * G3 + H + j];
            float wn = sWih[i * G3 + 2 * H + j];
            u64 wr2 = pk2(wr, wr), wz2 = pk2(wz, wz), wn2 = pk2(wn, wn);
            const ulonglong2* xp = (const ulonglong2*)(sx + i * NB);
#pragma unroll
            for (int q = 0; q < 4; q++) {
                ulonglong2 hq = xp[q];
                fma2(ar[2 * q],     hq.x, wr2);  fma2(ar[2 * q + 1], hq.y, wr2);
                fma2(az[2 * q],     hq.x, wz2);  fma2(az[2 * q + 1], hq.y, wz2);
                fma2(axn[2 * q],    hq.x, wn2);  fma2(axn[2 * q + 1], hq.y, wn2);
            }
        }

        // hidden projection, K = 256
        gemm_k(g_Wt_hh0, sh_h, ar, az, ahn, j);
        __syncthreads();   // everyone done reading sh_h

        float* out = &g_h1[((size_t)(t * NBLK + blockIdx.x) * H + j) * NB];
        float hnew[NB];
#pragma unroll
        for (int p = 0; p < 8; p++) {
            float2 r2 = up2(ar[p]), z2 = up2(az[p]), x2 = up2(axn[p]), h2 = up2(ahn[p]);
            float r0 = sigf(r2.x), z0 = sigf(z2.x);
            float n0 = tanhf_fast(x2.x + r0 * h2.x);
            hnew[2 * p] = n0 + z0 * (hreg[2 * p] - n0);
            float r1 = sigf(r2.y), z1 = sigf(z2.y);
            float n1 = tanhf_fast(x2.y + r1 * h2.y);
            hnew[2 * p + 1] = n1 + z1 * (hreg[2 * p + 1] - n1);
        }
#pragma unroll
        for (int b = 0; b < NB; b++) {
            hreg[b] = hnew[b];
            sh_h[j * NB + b] = hnew[b];
            out[b] = hnew[b];
        }
        __syncthreads();
    }
}

// ---------------- layer 1: fused input proj (K=256 from staged h1) + recurrence ----------------
__global__ __launch_bounds__(NTHR, 1)
void k_gru1(const float* __restrict__ bih, const float* __restrict__ bhh) {
    __shared__ float sh_h[H * NB];   // [c][b]
    __shared__ float sx[H * NB];     // staged h1[t] tile, already [c][b]

    const int j = threadIdx.x;
    const int bbase = blockIdx.x * NB;

    for (int idx = j; idx < H * NB; idx += NTHR) sh_h[idx] = 0.f;

    float hreg[NB];
#pragma unroll
    for (int b = 0; b < NB; b++) hreg[b] = 0.f;

    const float brz = bih[j] + bhh[j];
    const float bzz = bih[H + j] + bhh[H + j];
    const float bxn = bih[2 * H + j];
    const float bhn = bhh[2 * H + j];
    __syncthreads();

    for (int t = 0; t < T_STEPS; t++) {
        // stage h1[t] tile (written by layer 0 in [c][b] layout, so plain vector copy)
        const float4* src = (const float4*)&g_h1[(size_t)(t * NBLK + blockIdx.x) * H * NB];
        float4* dst = (float4*)sx;
        for (int idx = j; idx < (H * NB) / 4; idx += NTHR) dst[idx] = src[idx];
        __syncthreads();

        u64 ar[8], az[8], axn[8], ahn[8];
#pragma unroll
        for (int p = 0; p < 8; p++) {
            ar[p] = pk2(brz, brz); az[p] = pk2(bzz, bzz);
            axn[p] = pk2(bxn, bxn); ahn[p] = pk2(bhn, bhn);
        }

        gemm_k(g_Wt_ih1, sx,   ar, az, axn, j);   // input projection (K=256)
        gemm_k(g_Wt_hh1, sh_h, ar, az, ahn, j);   // hidden projection (K=256)
        __syncthreads();

        float hnew[NB];
#pragma unroll
        for (int p = 0; p < 8; p++) {
            float2 r2 = up2(ar[p]), z2 = up2(az[p]), x2 = up2(axn[p]), h2 = up2(ahn[p]);
            float r0 = sigf(r2.x), z0 = sigf(z2.x);
            float n0 = tanhf_fast(x2.x + r0 * h2.x);
            hnew[2 * p] = n0 + z0 * (hreg[2 * p] - n0);
            float r1 = sigf(r2.y), z1 = sigf(z2.y);
            float n1 = tanhf_fast(x2.y + r1 * h2.y);
            hnew[2 * p + 1] = n1 + z1 * (hreg[2 * p + 1] - n1);
        }
#pragma unroll
        for (int b = 0; b < NB; b++) {
            hreg[b] = hnew[b];
            sh_h[j * NB + b] = hnew[b];
        }
        if (t == T_STEPS - 1) {
#pragma unroll
            for (int b = 0; b < NB; b++) g_h2[(size_t)(bbase + b) * H + j] = hreg[b];
        }
        __syncthreads();
    }
}

// ---------------- FC head: logits = h2 @ fc_w^T + fc_b ; out = sigmoid*2-1 ----------------
__global__ void k_fc(const float* __restrict__ fcw, const float* __restrict__ fcb,
                     float* __restrict__ out) {
    int warp = threadIdx.x >> 5, lane = threadIdx.x & 31;
    int row = blockIdx.x * 8 + warp;
    const float* h = &g_h2[(size_t)row * H];
    float a0 = 0.f, a1 = 0.f, a2 = 0.f, a3 = 0.f;
    for (int k = lane; k < H; k += 32) {
        float hv = h[k];
        a0 += hv * fcw[k];
        a1 += hv * fcw[H + k];
        a2 += hv * fcw[2 * H + k];
        a3 += hv * fcw[3 * H + k];
    }
#pragma unroll
    for (int off = 16; off; off >>= 1) {
        a0 += __shfl_xor_sync(0xffffffffu, a0, off);
        a1 += __shfl_xor_sync(0xffffffffu, a1, off);
        a2 += __shfl_xor_sync(0xffffffffu, a2, off);
        a3 += __shfl_xor_sync(0xffffffffu, a3, off);
    }
    if (lane == 0) {
        float l0 = a0 + fcb[0], l1 = a1 + fcb[1], l2 = a2 + fcb[2], l3 = a3 + fcb[3];
        out[row * 4 + 0] = 2.f / (1.f + expf(-l0)) - 1.f;
        out[row * 4 + 1] = 2.f / (1.f + expf(-l1)) - 1.f;
        out[row * 4 + 2] = 2.f / (1.f + expf(-l2)) - 1.f;
        out[row * 4 + 3] = 2.f / (1.f + expf(-l3)) - 1.f;
    }
}

extern "C" void kernel_launch(void* const* d_in, const int* in_sizes, int n_in,
                              void* d_out, int out_size) {
    const float* x    = (const float*)d_in[0];
    const float* Wih0 = (const float*)d_in[1];
    const float* Whh0 = (const float*)d_in[2];
    const float* bih0 = (const float*)d_in[3];
    const float* bhh0 = (const float*)d_in[4];
    const float* Wih1 = (const float*)d_in[5];
    const float* Whh1 = (const float*)d_in[6];
    const float* bih1 = (const float*)d_in[7];
    const float* bhh1 = (const float*)d_in[8];
    const float* fcw  = (const float*)d_in[9];
    const float* fcb  = (const float*)d_in[10];
    float* out = (float*)d_out;

    static int smem_set = 0;
    const int gru0_smem = (IN0 * G3 + H * NB + IN0 * NB) * (int)sizeof(float); // 72832 B
    if (!smem_set) {
        cudaFuncSetAttribute(k_gru0, cudaFuncAttributeMaxDynamicSharedMemorySize, gru0_smem);
        smem_set = 1;
    }

    k_transpose<<<G3, 256>>>(Whh0, 0);
    k_transpose<<<G3, 256>>>(Whh1, 1);
    k_transpose<<<G3, 256>>>(Wih1, 2);
    k_gru0<<<NBLK, NTHR, gru0_smem>>>(x, Wih0, bih0, bhh0);
    k_gru1<<<NBLK, NTHR>>>(bih1, bhh1);
    k_fc<<<BATCH / 8, 256>>>(fcw, fcb, out);
}

// round 2
// speedup vs baseline: 1.0311x; 1.0311x over previous
#include <cuda_runtime.h>
#include <cstddef>

// Problem dims (fixed by the problem)
#define T_STEPS 128
#define BATCH   2048
#define IN0     18
#define H       256
#define G3      768   // 3*H
#define NB      16    // batch rows per block tile
#define NBT     8     // batch rows per thread (NB/2)
#define NBLK    (BATCH / NB)   // 128 blocks
#define NTHR    512   // (bh, j): bh = tid>>8, j = tid&255

typedef unsigned long long u64;

// ---------------- scratch (static __device__, no allocations) ----------------
__device__ float g_Wt_hh0[H * G3];   // W_hh0 transposed to [k][g]
__device__ float g_Wt_hh1[H * G3];
__device__ float g_Wt_ih1[H * G3];
// layer-0 outputs, tiled layout: [t][blk][c][b]  (c = hidden channel, b = 0..15)
__device__ float g_h1[(size_t)T_STEPS * NBLK * H * NB];
__device__ float g_h2[BATCH * H];    // layer-1 final hidden, [b][c]

// ---------------- packed fp32x2 helpers (Blackwell FFMA2) ----------------
__device__ __forceinline__ u64 pk2(float a, float b) {
    u64 r; asm("mov.b64 %0, {%1, %2};" : "=l"(r) : "f"(a), "f"(b)); return r;
}
__device__ __forceinline__ void fma2(u64& d, u64 a, u64 b) {
    asm("fma.rn.f32x2 %0, %1, %2, %0;" : "+l"(d) : "l"(a), "l"(b));
}
__device__ __forceinline__ float2 up2(u64 p) {
    float2 f; asm("mov.b64 {%0, %1}, %2;" : "=f"(f.x), "=f"(f.y) : "l"(p)); return f;
}

__device__ __forceinline__ float sigf(float x) {
    return __fdividef(1.f, 1.f + __expf(-x));
}
__device__ __forceinline__ float tanhf_fast(float x) {
    return 2.f * sigf(2.f * x) - 1.f;
}

// ---------------- transpose [768x256] -> [256x768] ----------------
__global__ void k_transpose(const float* __restrict__ src, int which) {
    float* dst = (which == 0) ? g_Wt_hh0 : (which == 1) ? g_Wt_hh1 : g_Wt_ih1;
    int idx = blockIdx.x * 256 + threadIdx.x;   // grid = 768 blocks, exact
    int k = idx / G3;
    int g = idx - k * G3;
    dst[idx] = src[g * H + k];
}

// Core hidden GEMM: acc[g][b] += sum_k sbuf[k][b] * Wt[k][g]  for g in {j, H+j, 2H+j}
// sbuf already offset by bh*NBT; accumulates NBT=8 batch elems per thread.
__device__ __forceinline__ void gemm_k(const float* __restrict__ Wt,
                                       const float* sbuf,  // smem, [k][NB] layout (+bh*8)
                                       u64* __restrict__ ar, u64* __restrict__ az,
                                       u64* __restrict__ an, int j) {
#pragma unroll 4
    for (int k = 0; k < H; k++) {
        const float* wp = Wt + k * G3 + j;
        float wr = __ldg(wp), wz = __ldg(wp + H), wn = __ldg(wp + 2 * H);
        u64 wr2 = pk2(wr, wr), wz2 = pk2(wz, wz), wn2 = pk2(wn, wn);
        const ulonglong2* hp = (const ulonglong2*)(sbuf + k * NB);
        ulonglong2 h0 = hp[0];   // 8 floats = 4 fp32x2 pairs
        fma2(ar[0], h0.x, wr2);  fma2(ar[1], h0.y, wr2);
        fma2(az[0], h0.x, wz2);  fma2(az[1], h0.y, wz2);
        fma2(an[0], h0.x, wn2);  fma2(an[1], h0.y, wn2);
        ulonglong2 h1 = hp[1];
        fma2(ar[2], h1.x, wr2);  fma2(ar[3], h1.y, wr2);
        fma2(az[2], h1.x, wz2);  fma2(az[3], h1.y, wz2);
        fma2(an[2], h1.x, wn2);  fma2(an[3], h1.y, wn2);
    }
}

// Shared epilogue: gates -> hnew[8], update hreg
__device__ __forceinline__ void epilogue(u64* ar, u64* az, u64* axn, u64* ahn,
                                         float* hreg, float* hnew) {
#pragma unroll
    for (int p = 0; p < 4; p++) {
        float2 r2 = up2(ar[p]), z2 = up2(az[p]), x2 = up2(axn[p]), h2 = up2(ahn[p]);
        float r0 = sigf(r2.x), z0 = sigf(z2.x);
        float n0 = tanhf_fast(x2.x + r0 * h2.x);
        hnew[2 * p] = n0 + z0 * (hreg[2 * p] - n0);
        float r1 = sigf(r2.y), z1 = sigf(z2.y);
        float n1 = tanhf_fast(x2.y + r1 * h2.y);
        hnew[2 * p + 1] = n1 + z1 * (hreg[2 * p + 1] - n1);
    }
#pragma unroll
    for (int b = 0; b < NBT; b++) hreg[b] = hnew[b];
}

// ---------------- layer 0: fused input proj (K=18, smem weights) + recurrence ----------------
__global__ __launch_bounds__(NTHR, 1)
void k_gru0(const float* __restrict__ x, const float* __restrict__ Wih,
            const float* __restrict__ bih, const float* __restrict__ bhh) {
    extern __shared__ float smem[];
    float* sWih = smem;                    // [i][g], 18*768 = 13824 floats
    float* sh_h = smem + IN0 * G3;         // [c][b], 256*16  = 4096 floats
    float* sx   = sh_h + H * NB;           // [i][b], 18*16   = 288 floats

    const int tid = threadIdx.x;
    const int j  = tid & 255;
    const int bh = tid >> 8;               // 0 or 1
    const int bo = bh * NBT;               // batch offset within tile
    const int bbase = blockIdx.x * NB;

    // stage W_ih0 transposed into smem
    for (int idx = tid; idx < IN0 * G3; idx += NTHR) {
        int i = idx / G3, g = idx - i * G3;
        sWih[idx] = Wih[g * IN0 + i];
    }
    for (int idx = tid; idx < H * NB; idx += NTHR) sh_h[idx] = 0.f;

    float hreg[NBT];
#pragma unroll
    for (int b = 0; b < NBT; b++) hreg[b] = 0.f;

    const float brz = bih[j] + bhh[j];
    const float bzz = bih[H + j] + bhh[H + j];
    const float bxn = bih[2 * H + j];
    const float bhn = bhh[2 * H + j];
    __syncthreads();

    for (int t = 0; t < T_STEPS; t++) {
        // stage x[t] tile, transposed to [i][b]
        for (int idx = tid; idx < IN0 * NB; idx += NTHR) {
            int b = idx / IN0, i = idx - b * IN0;
            sx[i * NB + b] = x[((size_t)(t * BATCH) + bbase + b) * IN0 + i];
        }
        __syncthreads();

        u64 ar[4], az[4], axn[4], ahn[4];
#pragma unroll
        for (int p = 0; p < 4; p++) {
            ar[p] = pk2(brz, brz); az[p] = pk2(bzz, bzz);
            axn[p] = pk2(bxn, bxn); ahn[p] = pk2(bhn, bhn);
        }

        // input projection, K = 18 (smem weights)
        const float* sxo = sx + bo;
#pragma unroll
        for (int i = 0; i < IN0; i++) {
            float wr = sWih[i * G3 + j];
            float wz = sWih[i * G3 + H + j];
            float wn = sWih[i * G3 + 2 * H + j];
            u64 wr2 = pk2(wr, wr), wz2 = pk2(wz, wz), wn2 = pk2(wn, wn);
            const ulonglong2* xp = (const ulonglong2*)(sxo + i * NB);
            ulonglong2 h0 = xp[0], h1 = xp[1];
            fma2(ar[0], h0.x, wr2);  fma2(ar[1], h0.y, wr2);
            fma2(az[0], h0.x, wz2);  fma2(az[1], h0.y, wz2);
            fma2(axn[0], h0.x, wn2); fma2(axn[1], h0.y, wn2);
            fma2(ar[2], h1.x, wr2);  fma2(ar[3], h1.y, wr2);
            fma2(az[2], h1.x, wz2);  fma2(az[3], h1.y, wz2);
            fma2(axn[2], h1.x, wn2); fma2(axn[3], h1.y, wn2);
        }

        // hidden projection, K = 256
        gemm_k(g_Wt_hh0, sh_h + bo, ar, az, ahn, j);
        __syncthreads();   // everyone done reading sh_h

        float hnew[NBT];
        epilogue(ar, az, axn, ahn, hreg, hnew);

        float* out = &g_h1[((size_t)(t * NBLK + blockIdx.x) * H + j) * NB + bo];
        float4 v0 = make_float4(hnew[0], hnew[1], hnew[2], hnew[3]);
        float4 v1 = make_float4(hnew[4], hnew[5], hnew[6], hnew[7]);
        ((float4*)(sh_h + j * NB + bo))[0] = v0;
        ((float4*)(sh_h + j * NB + bo))[1] = v1;
        ((float4*)out)[0] = v0;
        ((float4*)out)[1] = v1;
        __syncthreads();
    }
}

// ---------------- layer 1: fused input proj (K=256 from staged h1) + recurrence ----------------
__global__ __launch_bounds__(NTHR, 1)
void k_gru1(const float* __restrict__ bih, const float* __restrict__ bhh) {
    __shared__ float sh_h[H * NB];   // [c][b]
    __shared__ float sx[H * NB];     // staged h1[t] tile, already [c][b]

    const int tid = threadIdx.x;
    const int j  = tid & 255;
    const int bh = tid >> 8;
    const int bo = bh * NBT;
    const int bbase = blockIdx.x * NB;

    for (int idx = tid; idx < H * NB; idx += NTHR) sh_h[idx] = 0.f;

    float hreg[NBT];
#pragma unroll
    for (int b = 0; b < NBT; b++) hreg[b] = 0.f;

    const float brz = bih[j] + bhh[j];
    const float bzz = bih[H + j] + bhh[H + j];
    const float bxn = bih[2 * H + j];
    const float bhn = bhh[2 * H + j];
    __syncthreads();

    for (int t = 0; t < T_STEPS; t++) {
        // stage h1[t] tile (written by layer 0 in [c][b] layout, so plain vector copy)
        const float4* src = (const float4*)&g_h1[(size_t)(t * NBLK + blockIdx.x) * H * NB];
        float4* dst = (float4*)sx;
        for (int idx = tid; idx < (H * NB) / 4; idx += NTHR) dst[idx] = src[idx];
        __syncthreads();

        u64 ar[4], az[4], axn[4], ahn[4];
#pragma unroll
        for (int p = 0; p < 4; p++) {
            ar[p] = pk2(brz, brz); az[p] = pk2(bzz, bzz);
            axn[p] = pk2(bxn, bxn); ahn[p] = pk2(bhn, bhn);
        }

        gemm_k(g_Wt_ih1, sx + bo,   ar, az, axn, j);   // input projection (K=256)
        gemm_k(g_Wt_hh1, sh_h + bo, ar, az, ahn, j);   // hidden projection (K=256)
        __syncthreads();

        float hnew[NBT];
        epilogue(ar, az, axn, ahn, hreg, hnew);

        ((float4*)(sh_h + j * NB + bo))[0] = make_float4(hnew[0], hnew[1], hnew[2], hnew[3]);
        ((float4*)(sh_h + j * NB + bo))[1] = make_float4(hnew[4], hnew[5], hnew[6], hnew[7]);
        if (t == T_STEPS - 1) {
#pragma unroll
            for (int b = 0; b < NBT; b++) g_h2[(size_t)(bbase + bo + b) * H + j] = hreg[b];
        }
        __syncthreads();
    }
}

// ---------------- FC head: logits = h2 @ fc_w^T + fc_b ; out = sigmoid*2-1 ----------------
__global__ void k_fc(const float* __restrict__ fcw, const float* __restrict__ fcb,
                     float* __restrict__ out) {
    int warp = threadIdx.x >> 5, lane = threadIdx.x & 31;
    int row = blockIdx.x * 8 + warp;
    const float* h = &g_h2[(size_t)row * H];
    float a0 = 0.f, a1 = 0.f, a2 = 0.f, a3 = 0.f;
    for (int k = lane; k < H; k += 32) {
        float hv = h[k];
        a0 += hv * fcw[k];
        a1 += hv * fcw[H + k];
        a2 += hv * fcw[2 * H + k];
        a3 += hv * fcw[3 * H + k];
    }
#pragma unroll
    for (int off = 16; off; off >>= 1) {
        a0 += __shfl_xor_sync(0xffffffffu, a0, off);
        a1 += __shfl_xor_sync(0xffffffffu, a1, off);
        a2 += __shfl_xor_sync(0xffffffffu, a2, off);
        a3 += __shfl_xor_sync(0xffffffffu, a3, off);
    }
    if (lane == 0) {
        float l0 = a0 + fcb[0], l1 = a1 + fcb[1], l2 = a2 + fcb[2], l3 = a3 + fcb[3];
        out[row * 4 + 0] = 2.f / (1.f + expf(-l0)) - 1.f;
        out[row * 4 + 1] = 2.f / (1.f + expf(-l1)) - 1.f;
        out[row * 4 + 2] = 2.f / (1.f + expf(-l2)) - 1.f;
        out[row * 4 + 3] = 2.f / (1.f + expf(-l3)) - 1.f;
    }
}

extern "C" void kernel_launch(void* const* d_in, const int* in_sizes, int n_in,
                              void* d_out, int out_size) {
    const float* x    = (const float*)d_in[0];
    const float* Wih0 = (const float*)d_in[1];
    const float* Whh0 = (const float*)d_in[2];
    const float* bih0 = (const float*)d_in[3];
    const float* bhh0 = (const float*)d_in[4];
    const float* Wih1 = (const float*)d_in[5];
    const float* Whh1 = (const float*)d_in[6];
    const float* bih1 = (const float*)d_in[7];
    const float* bhh1 = (const float*)d_in[8];
    const float* fcw  = (const float*)d_in[9];
    const float* fcb  = (const float*)d_in[10];
    float* out = (float*)d_out;

    static int smem_set = 0;
    const int gru0_smem = (IN0 * G3 + H * NB + IN0 * NB) * (int)sizeof(float); // 72832 B
    if (!smem_set) {
        cudaFuncSetAttribute(k_gru0, cudaFuncAttributeMaxDynamicSharedMemorySize, gru0_smem);
        smem_set = 1;
    }

    k_transpose<<<G3, 256>>>(Whh0, 0);
    k_transpose<<<G3, 256>>>(Whh1, 1);
    k_transpose<<<G3, 256>>>(Wih1, 2);
    k_gru0<<<NBLK, NTHR, gru0_smem>>>(x, Wih0, bih0, bhh0);
    k_gru1<<<NBLK, NTHR>>>(bih1, bhh1);
    k_fc<<<BATCH / 8, 256>>>(fcw, fcb, out);
}

// round 3
// speedup vs baseline: 1.4634x; 1.4192x over previous
#include <cuda_runtime.h>
#include <cstddef>

// Problem dims (fixed)
#define T_STEPS 128
#define BATCH   2048
#define IN0     18
#define H       256
#define G3      768   // 3*H
#define NB      16    // batch rows per block tile
#define NBT     8     // batch rows per thread (NB/2)
#define NBLK    (BATCH / NB)   // 128 blocks
#define NTHR    512   // (bh, j): bh = tid>>8, j = tid&255

typedef unsigned long long u64;

// ---------------- scratch ----------------
__device__ float g_Wt_hh0[H * G3];   // transposed to [k][g]
__device__ float g_Wt_hh1[H * G3];
__device__ float g_Wt_ih1[H * G3];
__device__ float g_h2[BATCH * H];    // layer-1 final hidden, [b][c]

// ---------------- packed fp32x2 helpers ----------------
__device__ __forceinline__ u64 pk2(float a, float b) {
    u64 r; asm("mov.b64 %0, {%1, %2};" : "=l"(r) : "f"(a), "f"(b)); return r;
}
__device__ __forceinline__ void fma2(u64& d, u64 a, u64 b) {
    asm("fma.rn.f32x2 %0, %1, %2, %0;" : "+l"(d) : "l"(a), "l"(b));
}
__device__ __forceinline__ float2 up2(u64 p) {
    float2 f; asm("mov.b64 {%0, %1}, %2;" : "=f"(f.x), "=f"(f.y) : "l"(p)); return f;
}
__device__ __forceinline__ float sigf(float x) {
    return __fdividef(1.f, 1.f + __expf(-x));
}
__device__ __forceinline__ float tanhf_fast(float x) {
    return 2.f * sigf(2.f * x) - 1.f;
}

// ---------------- transpose [768x256] -> [256x768] ----------------
__global__ void k_transpose(const float* __restrict__ src, int which) {
    float* dst = (which == 0) ? g_Wt_hh0 : (which == 1) ? g_Wt_hh1 : g_Wt_ih1;
    int idx = blockIdx.x * 256 + threadIdx.x;
    int k = idx / G3;
    int g = idx - k * G3;
    dst[idx] = src[g * H + k];
}

// ---- pipelined single-matrix gemm: acc += sbuf[k][:] * Wt[k][{j,H+j,2H+j}] ----
__device__ __forceinline__ void gemm_pipe1(const float* __restrict__ Wt,
                                           const float* __restrict__ sbuf,
                                           u64* __restrict__ ar, u64* __restrict__ az,
                                           u64* __restrict__ an, int j) {
    const float* wp = Wt + j;
    float wb[2][12];
#pragma unroll
    for (int kk = 0; kk < 4; kk++) {
        const float* p = wp + kk * G3;
        wb[0][kk * 3 + 0] = __ldg(p);
        wb[0][kk * 3 + 1] = __ldg(p + H);
        wb[0][kk * 3 + 2] = __ldg(p + 2 * H);
    }
#pragma unroll 2
    for (int c = 0; c < H / 4; c++) {
        const int cur = c & 1, nxt = cur ^ 1;
        if (c + 1 < H / 4) {
#pragma unroll
            for (int kk = 0; kk < 4; kk++) {
                const float* p = wp + ((c + 1) * 4 + kk) * G3;
                wb[nxt][kk * 3 + 0] = __ldg(p);
                wb[nxt][kk * 3 + 1] = __ldg(p + H);
                wb[nxt][kk * 3 + 2] = __ldg(p + 2 * H);
            }
        }
#pragma unroll
        for (int kk = 0; kk < 4; kk++) {
            const int k = c * 4 + kk;
            float wr = wb[cur][kk * 3 + 0], wz = wb[cur][kk * 3 + 1], wn = wb[cur][kk * 3 + 2];
            u64 wr2 = pk2(wr, wr), wz2 = pk2(wz, wz), wn2 = pk2(wn, wn);
            const ulonglong2* hp = (const ulonglong2*)(sbuf + k * NB);
            ulonglong2 h0 = hp[0], h1v = hp[1];
            fma2(ar[0], h0.x, wr2);  fma2(ar[1], h0.y, wr2);
            fma2(az[0], h0.x, wz2);  fma2(az[1], h0.y, wz2);
            fma2(an[0], h0.x, wn2);  fma2(an[1], h0.y, wn2);
            fma2(ar[2], h1v.x, wr2); fma2(ar[3], h1v.y, wr2);
            fma2(az[2], h1v.x, wz2); fma2(az[3], h1v.y, wz2);
            fma2(an[2], h1v.x, wn2); fma2(an[3], h1v.y, wn2);
        }
    }
}

// ---- pipelined dual gemm (layer 1): input (Wti, sxb) + hidden (Wth, shb) ----
__device__ __forceinline__ void gemm_pipe2(const float* __restrict__ Wti,
                                           const float* __restrict__ Wth,
                                           const float* __restrict__ sxb,
                                           const float* __restrict__ shb,
                                           u64* __restrict__ ar, u64* __restrict__ az,
                                           u64* __restrict__ axn, u64* __restrict__ ahn,
                                           int j) {
    const float* wpi = Wti + j;
    const float* wph = Wth + j;
    float wb[2][24];
#pragma unroll
    for (int kk = 0; kk < 4; kk++) {
        const float* pi = wpi + kk * G3;
        const float* ph = wph + kk * G3;
        wb[0][kk * 6 + 0] = __ldg(pi);
        wb[0][kk * 6 + 1] = __ldg(pi + H);
        wb[0][kk * 6 + 2] = __ldg(pi + 2 * H);
        wb[0][kk * 6 + 3] = __ldg(ph);
        wb[0][kk * 6 + 4] = __ldg(ph + H);
        wb[0][kk * 6 + 5] = __ldg(ph + 2 * H);
    }
#pragma unroll 2
    for (int c = 0; c < H / 4; c++) {
        const int cur = c & 1, nxt = cur ^ 1;
        if (c + 1 < H / 4) {
#pragma unroll
            for (int kk = 0; kk < 4; kk++) {
                const float* pi = wpi + ((c + 1) * 4 + kk) * G3;
                const float* ph = wph + ((c + 1) * 4 + kk) * G3;
                wb[nxt][kk * 6 + 0] = __ldg(pi);
                wb[nxt][kk * 6 + 1] = __ldg(pi + H);
                wb[nxt][kk * 6 + 2] = __ldg(pi + 2 * H);
                wb[nxt][kk * 6 + 3] = __ldg(ph);
                wb[nxt][kk * 6 + 4] = __ldg(ph + H);
                wb[nxt][kk * 6 + 5] = __ldg(ph + 2 * H);
            }
        }
#pragma unroll
        for (int kk = 0; kk < 4; kk++) {
            const int k = c * 4 + kk;
            u64 wir2 = pk2(wb[cur][kk * 6 + 0], wb[cur][kk * 6 + 0]);
            u64 wiz2 = pk2(wb[cur][kk * 6 + 1], wb[cur][kk * 6 + 1]);
            u64 win2 = pk2(wb[cur][kk * 6 + 2], wb[cur][kk * 6 + 2]);
            u64 whr2 = pk2(wb[cur][kk * 6 + 3], wb[cur][kk * 6 + 3]);
            u64 whz2 = pk2(wb[cur][kk * 6 + 4], wb[cur][kk * 6 + 4]);
            u64 whn2 = pk2(wb[cur][kk * 6 + 5], wb[cur][kk * 6 + 5]);
            const ulonglong2* xp = (const ulonglong2*)(sxb + k * NB);
            const ulonglong2* hp = (const ulonglong2*)(shb + k * NB);
            ulonglong2 x0 = xp[0], x1 = xp[1];
            ulonglong2 h0 = hp[0], h1v = hp[1];
            fma2(ar[0], x0.x, wir2);  fma2(ar[1], x0.y, wir2);
            fma2(ar[2], x1.x, wir2);  fma2(ar[3], x1.y, wir2);
            fma2(az[0], x0.x, wiz2);  fma2(az[1], x0.y, wiz2);
            fma2(az[2], x1.x, wiz2);  fma2(az[3], x1.y, wiz2);
            fma2(axn[0], x0.x, win2); fma2(axn[1], x0.y, win2);
            fma2(axn[2], x1.x, win2); fma2(axn[3], x1.y, win2);
            fma2(ar[0], h0.x, whr2);  fma2(ar[1], h0.y, whr2);
            fma2(ar[2], h1v.x, whr2); fma2(ar[3], h1v.y, whr2);
            fma2(az[0], h0.x, whz2);  fma2(az[1], h0.y, whz2);
            fma2(az[2], h1v.x, whz2); fma2(az[3], h1v.y, whz2);
            fma2(ahn[0], h0.x, whn2); fma2(ahn[1], h0.y, whn2);
            fma2(ahn[2], h1v.x, whn2); fma2(ahn[3], h1v.y, whn2);
        }
    }
}

// gates -> hnew[8]; old h read from smem slice (thread-private)
__device__ __forceinline__ void epilogue(u64* ar, u64* az, u64* axn, u64* ahn,
                                         const float* hold, float* hnew) {
#pragma unroll
    for (int p = 0; p < 4; p++) {
        float2 r2 = up2(ar[p]), z2 = up2(az[p]), x2 = up2(axn[p]), h2 = up2(ahn[p]);
        float r0 = sigf(r2.x), z0 = sigf(z2.x);
        float n0 = tanhf_fast(x2.x + r0 * h2.x);
        hnew[2 * p] = n0 + z0 * (hold[2 * p] - n0);
        float r1 = sigf(r2.y), z1 = sigf(z2.y);
        float n1 = tanhf_fast(x2.y + r1 * h2.y);
        hnew[2 * p + 1] = n1 + z1 * (hold[2 * p + 1] - n1);
    }
}

// ---------------- fused 2-layer GRU, persistent per batch tile ----------------
__global__ __launch_bounds__(NTHR, 1)
void k_gru(const float* __restrict__ x, const float* __restrict__ Wih0,
           const float* __restrict__ bih0, const float* __restrict__ bhh0,
           const float* __restrict__ bih1, const float* __restrict__ bhh1) {
    extern __shared__ float smem[];
    float* sWih = smem;                    // [i][g], 18*768
    float* sh0  = smem + IN0 * G3;         // layer-0 h, [c][b], 256*16
    float* sh1  = sh0 + H * NB;            // layer-1 h, [c][b]
    float* sx   = sh1 + H * NB;            // x tile, [i][b], 18*16

    const int tid = threadIdx.x;
    const int j  = tid & 255;
    const int bh = tid >> 8;
    const int bo = bh * NBT;
    const int bbase = blockIdx.x * NB;

    for (int idx = tid; idx < IN0 * G3; idx += NTHR) {
        int i = idx / G3, g = idx - i * G3;
        sWih[idx] = Wih0[g * IN0 + i];
    }
    for (int idx = tid; idx < 2 * H * NB; idx += NTHR) sh0[idx] = 0.f;  // sh0+sh1 contiguous

    const float brz0 = bih0[j] + bhh0[j];
    const float bzz0 = bih0[H + j] + bhh0[H + j];
    const float bxn0 = bih0[2 * H + j];
    const float bhn0 = bhh0[2 * H + j];
    const float brz1 = bih1[j] + bhh1[j];
    const float bzz1 = bih1[H + j] + bhh1[H + j];
    const float bxn1 = bih1[2 * H + j];
    const float bhn1 = bhh1[2 * H + j];
    __syncthreads();

    float* myh0 = sh0 + j * NB + bo;   // this thread's private h slices
    float* myh1 = sh1 + j * NB + bo;

    for (int t = 0; t < T_STEPS; t++) {
        // stage x[t] tile, transposed to [i][b]
        for (int idx = tid; idx < IN0 * NB; idx += NTHR) {
            int b = idx / IN0, i = idx - b * IN0;
            sx[i * NB + b] = x[((size_t)(t * BATCH) + bbase + b) * IN0 + i];
        }
        __syncthreads();

        // ---------- layer 0 ----------
        u64 ar[4], az[4], axn[4], ahn[4];
#pragma unroll
        for (int p = 0; p < 4; p++) {
            ar[p] = pk2(brz0, brz0); az[p] = pk2(bzz0, bzz0);
            axn[p] = pk2(bxn0, bxn0); ahn[p] = pk2(bhn0, bhn0);
        }
        // input projection K=18 from smem
        const float* sxo = sx + bo;
#pragma unroll
        for (int i = 0; i < IN0; i++) {
            float wr = sWih[i * G3 + j];
            float wz = sWih[i * G3 + H + j];
            float wn = sWih[i * G3 + 2 * H + j];
            u64 wr2 = pk2(wr, wr), wz2 = pk2(wz, wz), wn2 = pk2(wn, wn);
            const ulonglong2* xp = (const ulonglong2*)(sxo + i * NB);
            ulonglong2 v0 = xp[0], v1 = xp[1];
            fma2(ar[0], v0.x, wr2);  fma2(ar[1], v0.y, wr2);
            fma2(az[0], v0.x, wz2);  fma2(az[1], v0.y, wz2);
            fma2(axn[0], v0.x, wn2); fma2(axn[1], v0.y, wn2);
            fma2(ar[2], v1.x, wr2);  fma2(ar[3], v1.y, wr2);
            fma2(az[2], v1.x, wz2);  fma2(az[3], v1.y, wz2);
            fma2(axn[2], v1.x, wn2); fma2(axn[3], v1.y, wn2);
        }
        gemm_pipe1(g_Wt_hh0, sh0 + bo, ar, az, ahn, j);
        __syncthreads();   // all warps done reading sh0

        {
            float hnew[NBT];
            epilogue(ar, az, axn, ahn, myh0, hnew);
            ((float4*)myh0)[0] = make_float4(hnew[0], hnew[1], hnew[2], hnew[3]);
            ((float4*)myh0)[1] = make_float4(hnew[4], hnew[5], hnew[6], hnew[7]);
        }
        __syncthreads();   // sh0 (= layer-1 input) ready

        // ---------- layer 1 ----------
#pragma unroll
        for (int p = 0; p < 4; p++) {
            ar[p] = pk2(brz1, brz1); az[p] = pk2(bzz1, bzz1);
            axn[p] = pk2(bxn1, bxn1); ahn[p] = pk2(bhn1, bhn1);
        }
        gemm_pipe2(g_Wt_ih1, g_Wt_hh1, sh0 + bo, sh1 + bo, ar, az, axn, ahn, j);
        __syncthreads();   // all warps done reading sh1

        {
            float hnew[NBT];
            epilogue(ar, az, axn, ahn, myh1, hnew);
            ((float4*)myh1)[0] = make_float4(hnew[0], hnew[1], hnew[2], hnew[3]);
            ((float4*)myh1)[1] = make_float4(hnew[4], hnew[5], hnew[6], hnew[7]);
            if (t == T_STEPS - 1) {
#pragma unroll
                for (int b = 0; b < NBT; b++)
                    g_h2[(size_t)(bbase + bo + b) * H + j] = hnew[b];
            }
        }
        __syncthreads();   // sh1 writes visible before next step's gemm
    }
}

// ---------------- FC head ----------------
__global__ void k_fc(const float* __restrict__ fcw, const float* __restrict__ fcb,
                     float* __restrict__ out) {
    int warp = threadIdx.x >> 5, lane = threadIdx.x & 31;
    int row = blockIdx.x * 8 + warp;
    const float* h = &g_h2[(size_t)row * H];
    float a0 = 0.f, a1 = 0.f, a2 = 0.f, a3 = 0.f;
    for (int k = lane; k < H; k += 32) {
        float hv = h[k];
        a0 += hv * fcw[k];
        a1 += hv * fcw[H + k];
        a2 += hv * fcw[2 * H + k];
        a3 += hv * fcw[3 * H + k];
    }
#pragma unroll
    for (int off = 16; off; off >>= 1) {
        a0 += __shfl_xor_sync(0xffffffffu, a0, off);
        a1 += __shfl_xor_sync(0xffffffffu, a1, off);
        a2 += __shfl_xor_sync(0xffffffffu, a2, off);
        a3 += __shfl_xor_sync(0xffffffffu, a3, off);
    }
    if (lane == 0) {
        float l0 = a0 + fcb[0], l1 = a1 + fcb[1], l2 = a2 + fcb[2], l3 = a3 + fcb[3];
        out[row * 4 + 0] = 2.f / (1.f + expf(-l0)) - 1.f;
        out[row * 4 + 1] = 2.f / (1.f + expf(-l1)) - 1.f;
        out[row * 4 + 2] = 2.f / (1.f + expf(-l2)) - 1.f;
        out[row * 4 + 3] = 2.f / (1.f + expf(-l3)) - 1.f;
    }
}

extern "C" void kernel_launch(void* const* d_in, const int* in_sizes, int n_in,
                              void* d_out, int out_size) {
    const float* x    = (const float*)d_in[0];
    const float* Wih0 = (const float*)d_in[1];
    const float* Whh0 = (const float*)d_in[2];
    const float* bih0 = (const float*)d_in[3];
    const float* bhh0 = (const float*)d_in[4];
    const float* Wih1 = (const float*)d_in[5];
    const float* Whh1 = (const float*)d_in[6];
    const float* bih1 = (const float*)d_in[7];
    const float* bhh1 = (const float*)d_in[8];
    const float* fcw  = (const float*)d_in[9];
    const float* fcb  = (const float*)d_in[10];
    float* out = (float*)d_out;

    const int gru_smem = (IN0 * G3 + 2 * H * NB + IN0 * NB) * (int)sizeof(float); // 89216 B
    static int smem_set = 0;
    if (!smem_set) {
        cudaFuncSetAttribute(k_gru, cudaFuncAttributeMaxDynamicSharedMemorySize, gru_smem);
        smem_set = 1;
    }

    k_transpose<<<G3, 256>>>(Whh0, 0);
    k_transpose<<<G3, 256>>>(Whh1, 1);
    k_transpose<<<G3, 256>>>(Wih1, 2);
    k_gru<<<NBLK, NTHR, gru_smem>>>(x, Wih0, bih0, bhh0, bih1, bhh1);
    k_fc<<<BATCH / 8, 256>>>(fcw, fcb, out);
}